// round 1
// baseline (speedup 1.0000x reference)
#include <cuda_runtime.h>
#include <cuda_bf16.h>
#include <cstddef>

// Problem constants
#define BB   512
#define KK   512
#define DIN  1024
#define DOUT 4096
#define C3K  1536          // 3*K
#define NROWS (BB*KK)      // 262144

// Scratch (static device globals — no allocation)
__device__ float g_y[BB * C3K];     // [b][o*512 + k], 3 MB
__device__ float g_stats[6];        // sum[3], sumsq[3]
__device__ float g_coef[6];         // scale[3], shift[3]

// ---------------------------------------------------------------------------
// Kernel A: y[b, o*K + k] = dot(x[b,k,:], W_emb[o,:]) + b_emb[o]
// One warp per row (b,k), grid-stride. W_emb held in registers (24 float4/lane).
// Also zeroes g_stats for this replay.
// ---------------------------------------------------------------------------
__global__ __launch_bounds__(256) void k_embed(const float* __restrict__ x,
                                               const float* __restrict__ Wemb,
                                               const float* __restrict__ bemb) {
    const int tid = threadIdx.x;
    if (blockIdx.x == 0 && tid < 6) g_stats[tid] = 0.0f;

    const int lane = tid & 31;

    // Register-resident W_emb: lane holds columns [j*128 + lane*4 .. +3] for j=0..7
    float4 w0[8], w1[8], w2[8];
    const float4* W4 = (const float4*)Wemb;
#pragma unroll
    for (int j = 0; j < 8; j++) {
        w0[j] = W4[      j * 32 + lane];
        w1[j] = W4[256 + j * 32 + lane];
        w2[j] = W4[512 + j * 32 + lane];
    }
    const float b0 = bemb[0], b1 = bemb[1], b2 = bemb[2];

    int gw = blockIdx.x * 8 + (tid >> 5);
    const int nw = gridDim.x * 8;

    for (int row = gw; row < NROWS; row += nw) {
        const float4* xr = (const float4*)x + (size_t)row * 256;
        float a0 = 0.f, a1 = 0.f, a2 = 0.f;
#pragma unroll
        for (int j = 0; j < 8; j++) {
            float4 xv = xr[j * 32 + lane];
            a0 += xv.x * w0[j].x + xv.y * w0[j].y + xv.z * w0[j].z + xv.w * w0[j].w;
            a1 += xv.x * w1[j].x + xv.y * w1[j].y + xv.z * w1[j].z + xv.w * w1[j].w;
            a2 += xv.x * w2[j].x + xv.y * w2[j].y + xv.z * w2[j].z + xv.w * w2[j].w;
        }
#pragma unroll
        for (int off = 16; off; off >>= 1) {
            a0 += __shfl_xor_sync(0xffffffffu, a0, off);
            a1 += __shfl_xor_sync(0xffffffffu, a1, off);
            a2 += __shfl_xor_sync(0xffffffffu, a2, off);
        }
        if (lane == 0) {
            const int b = row >> 9, k = row & 511;
            float* yb = g_y + (size_t)b * C3K + k;
            yb[0]    = a0 + b0;
            yb[512]  = a1 + b1;
            yb[1024] = a2 + b2;
        }
    }
}

// ---------------------------------------------------------------------------
// Kernel B1: per-channel sum / sumsq over g_y (channel = (flat%1536)/512)
// ---------------------------------------------------------------------------
__global__ __launch_bounds__(256) void k_stats() {
    float s[3] = {0.f, 0.f, 0.f};
    float q[3] = {0.f, 0.f, 0.f};
    const int stride = gridDim.x * blockDim.x;
    const float4* y4 = (const float4*)g_y;
    const int n4 = (BB * C3K) / 4;  // 196608
    for (int i = blockIdx.x * blockDim.x + threadIdx.x; i < n4; i += stride) {
        const int o = (i % 384) >> 7;   // ((i*4) % 1536) / 512
        float4 v = y4[i];
        s[o] += v.x + v.y + v.z + v.w;
        q[o] += v.x * v.x + v.y * v.y + v.z * v.z + v.w * v.w;
    }
#pragma unroll
    for (int off = 16; off; off >>= 1) {
#pragma unroll
        for (int o = 0; o < 3; o++) {
            s[o] += __shfl_xor_sync(0xffffffffu, s[o], off);
            q[o] += __shfl_xor_sync(0xffffffffu, q[o], off);
        }
    }
    __shared__ float rs[6];
    if (threadIdx.x < 6) rs[threadIdx.x] = 0.f;
    __syncthreads();
    if ((threadIdx.x & 31) == 0) {
#pragma unroll
        for (int o = 0; o < 3; o++) {
            atomicAdd(&rs[o], s[o]);
            atomicAdd(&rs[3 + o], q[o]);
        }
    }
    __syncthreads();
    if (threadIdx.x < 6) atomicAdd(&g_stats[threadIdx.x], rs[threadIdx.x]);
}

// ---------------------------------------------------------------------------
// Kernel B2: finalize BN affine: scale = gamma*rsqrt(var+eps), shift = beta - mean*scale
// ---------------------------------------------------------------------------
__global__ void k_final(const float* __restrict__ gamma, const float* __restrict__ beta) {
    const int o = threadIdx.x;
    if (o < 3) {
        const float n = (float)NROWS;
        float mean = g_stats[o] / n;
        float var  = g_stats[3 + o] / n - mean * mean;
        float sc   = gamma[o] * rsqrtf(var + 1e-5f);
        g_coef[o]     = sc;
        g_coef[3 + o] = beta[o] - mean * sc;
    }
}

// ---------------------------------------------------------------------------
// Kernel C: out[512,4096] = (g_y*scale+shift)[512,1536] @ W_fc2^T[1536,4096]
// 128x128x16 tiles, 256 threads, 8x8 microtiles. Norm folded into A-tile load
// (each 16-wide k-tile lies fully inside one channel: 512 % 16 == 0).
// ---------------------------------------------------------------------------
__global__ __launch_bounds__(256) void k_gemm2(const float* __restrict__ W,
                                               float* __restrict__ out) {
    __shared__ float As[16][132];
    __shared__ float Bs[16][132];

    const int tid = threadIdx.x;
    const int tx = tid & 15;      // N micro index
    const int ty = tid >> 4;      // M micro index
    const int bn = blockIdx.x;    // 0..31
    const int bm = blockIdx.y;    // 0..3

    const int lr = tid >> 2;           // loader row 0..63
    const int lc = (tid & 3) * 4;      // loader col (of 16)

    const float* Ap = g_y + ((size_t)(bm * 128 + lr)) * C3K + lc;
    const float* Bp = W   + ((size_t)(bn * 128 + lr)) * C3K + lc;

    float acc[8][8];
#pragma unroll
    for (int i = 0; i < 8; i++)
#pragma unroll
        for (int j = 0; j < 8; j++) acc[i][j] = 0.f;

    for (int kt = 0; kt < C3K / 16; kt++) {
        const int o = kt >> 5;                 // channel of this k-tile
        const float sc = g_coef[o];
        const float sh = g_coef[3 + o];

        float4 a0  = *(const float4*)(Ap + (size_t)kt * 16);
        float4 a1  = *(const float4*)(Ap + (size_t)kt * 16 + (size_t)64 * C3K);
        float4 bb0 = *(const float4*)(Bp + (size_t)kt * 16);
        float4 bb1 = *(const float4*)(Bp + (size_t)kt * 16 + (size_t)64 * C3K);

        __syncthreads();   // previous tile's compute done before overwrite

        As[lc + 0][lr]      = a0.x * sc + sh;
        As[lc + 1][lr]      = a0.y * sc + sh;
        As[lc + 2][lr]      = a0.z * sc + sh;
        As[lc + 3][lr]      = a0.w * sc + sh;
        As[lc + 0][lr + 64] = a1.x * sc + sh;
        As[lc + 1][lr + 64] = a1.y * sc + sh;
        As[lc + 2][lr + 64] = a1.z * sc + sh;
        As[lc + 3][lr + 64] = a1.w * sc + sh;

        Bs[lc + 0][lr]      = bb0.x;
        Bs[lc + 1][lr]      = bb0.y;
        Bs[lc + 2][lr]      = bb0.z;
        Bs[lc + 3][lr]      = bb0.w;
        Bs[lc + 0][lr + 64] = bb1.x;
        Bs[lc + 1][lr + 64] = bb1.y;
        Bs[lc + 2][lr + 64] = bb1.z;
        Bs[lc + 3][lr + 64] = bb1.w;

        __syncthreads();

#pragma unroll
        for (int kk = 0; kk < 16; kk++) {
            float4 xa0 = *(const float4*)&As[kk][ty * 8];
            float4 xa1 = *(const float4*)&As[kk][ty * 8 + 4];
            float4 xb0 = *(const float4*)&Bs[kk][tx * 8];
            float4 xb1 = *(const float4*)&Bs[kk][tx * 8 + 4];
            float ar[8] = {xa0.x, xa0.y, xa0.z, xa0.w, xa1.x, xa1.y, xa1.z, xa1.w};
            float br[8] = {xb0.x, xb0.y, xb0.z, xb0.w, xb1.x, xb1.y, xb1.z, xb1.w};
#pragma unroll
            for (int i = 0; i < 8; i++)
#pragma unroll
                for (int j = 0; j < 8; j++) acc[i][j] += ar[i] * br[j];
        }
    }

    float* Cp = out + ((size_t)(bm * 128 + ty * 8)) * DOUT + bn * 128 + tx * 8;
#pragma unroll
    for (int i = 0; i < 8; i++) {
        float4 v0 = make_float4(acc[i][0], acc[i][1], acc[i][2], acc[i][3]);
        float4 v1 = make_float4(acc[i][4], acc[i][5], acc[i][6], acc[i][7]);
        *(float4*)(Cp + (size_t)i * DOUT)     = v0;
        *(float4*)(Cp + (size_t)i * DOUT + 4) = v1;
    }
}

// ---------------------------------------------------------------------------
// Launch: x, W_emb, b_emb, gamma, beta, W_fc2 -> out[512*4096] fp32
// ---------------------------------------------------------------------------
extern "C" void kernel_launch(void* const* d_in, const int* in_sizes, int n_in,
                              void* d_out, int out_size) {
    const float* x     = (const float*)d_in[0];
    const float* Wemb  = (const float*)d_in[1];
    const float* bemb  = (const float*)d_in[2];
    const float* gamma = (const float*)d_in[3];
    const float* beta  = (const float*)d_in[4];
    const float* Wfc2  = (const float*)d_in[5];
    float* out = (float*)d_out;

    k_embed<<<1184, 256>>>(x, Wemb, bemb);
    k_stats<<<96, 256>>>();
    k_final<<<1, 32>>>(gamma, beta);
    k_gemm2<<<dim3(32, 4), 256>>>(Wfc2, out);
}

// round 3
// speedup vs baseline: 1.0729x; 1.0729x over previous
#include <cuda_runtime.h>
#include <cuda_bf16.h>
#include <cstdint>
#include <cstddef>

// Problem constants
#define BB   512
#define KK   512
#define DIN  1024
#define DOUT 4096
#define C3K  1536          // 3*K
#define NROWS (BB*KK)      // 262144
#define NKT  (C3K/16)      // 96 k-tiles

// Scratch (static device globals — no allocation)
__device__ float g_y[BB * C3K];     // [b][o*512 + k], 3 MB
__device__ float g_stats[6];        // sum[3], sumsq[3]
__device__ float g_coef[6];         // scale[3], shift[3]

// ---------------------------------------------------------------------------
// Kernel A: y[b, o*K + k] = dot(x[b,k,:], W_emb[o,:]) + b_emb[o]
// One warp per row (b,k), grid-stride. W_emb register-resident.
// ---------------------------------------------------------------------------
__global__ __launch_bounds__(256) void k_embed(const float* __restrict__ x,
                                               const float* __restrict__ Wemb,
                                               const float* __restrict__ bemb) {
    const int tid = threadIdx.x;
    if (blockIdx.x == 0 && tid < 6) g_stats[tid] = 0.0f;
    const int lane = tid & 31;

    float4 w0[8], w1[8], w2[8];
    const float4* W4 = (const float4*)Wemb;
#pragma unroll
    for (int j = 0; j < 8; j++) {
        w0[j] = W4[      j * 32 + lane];
        w1[j] = W4[256 + j * 32 + lane];
        w2[j] = W4[512 + j * 32 + lane];
    }
    const float b0 = bemb[0], b1 = bemb[1], b2 = bemb[2];

    int gw = blockIdx.x * 8 + (tid >> 5);
    const int nw = gridDim.x * 8;
    for (int row = gw; row < NROWS; row += nw) {
        const float4* xr = (const float4*)x + (size_t)row * 256;
        float a0 = 0.f, a1 = 0.f, a2 = 0.f;
#pragma unroll
        for (int j = 0; j < 8; j++) {
            float4 xv = xr[j * 32 + lane];
            a0 += xv.x * w0[j].x + xv.y * w0[j].y + xv.z * w0[j].z + xv.w * w0[j].w;
            a1 += xv.x * w1[j].x + xv.y * w1[j].y + xv.z * w1[j].z + xv.w * w1[j].w;
            a2 += xv.x * w2[j].x + xv.y * w2[j].y + xv.z * w2[j].z + xv.w * w2[j].w;
        }
#pragma unroll
        for (int off = 16; off; off >>= 1) {
            a0 += __shfl_xor_sync(0xffffffffu, a0, off);
            a1 += __shfl_xor_sync(0xffffffffu, a1, off);
            a2 += __shfl_xor_sync(0xffffffffu, a2, off);
        }
        if (lane == 0) {
            const int b = row >> 9, k = row & 511;
            float* yb = g_y + (size_t)b * C3K + k;
            yb[0]    = a0 + b0;
            yb[512]  = a1 + b1;
            yb[1024] = a2 + b2;
        }
    }
}

// ---------------------------------------------------------------------------
// Kernel B1: per-channel sum / sumsq over g_y
// ---------------------------------------------------------------------------
__global__ __launch_bounds__(256) void k_stats() {
    float s[3] = {0.f, 0.f, 0.f};
    float q[3] = {0.f, 0.f, 0.f};
    const int stride = gridDim.x * blockDim.x;
    const float4* y4 = (const float4*)g_y;
    const int n4 = (BB * C3K) / 4;
    for (int i = blockIdx.x * blockDim.x + threadIdx.x; i < n4; i += stride) {
        const int o = (i % 384) >> 7;
        float4 v = y4[i];
        s[o] += v.x + v.y + v.z + v.w;
        q[o] += v.x * v.x + v.y * v.y + v.z * v.z + v.w * v.w;
    }
#pragma unroll
    for (int off = 16; off; off >>= 1) {
#pragma unroll
        for (int o = 0; o < 3; o++) {
            s[o] += __shfl_xor_sync(0xffffffffu, s[o], off);
            q[o] += __shfl_xor_sync(0xffffffffu, q[o], off);
        }
    }
    __shared__ float rs[6];
    if (threadIdx.x < 6) rs[threadIdx.x] = 0.f;
    __syncthreads();
    if ((threadIdx.x & 31) == 0) {
#pragma unroll
        for (int o = 0; o < 3; o++) {
            atomicAdd(&rs[o], s[o]);
            atomicAdd(&rs[3 + o], q[o]);
        }
    }
    __syncthreads();
    if (threadIdx.x < 6) atomicAdd(&g_stats[threadIdx.x], rs[threadIdx.x]);
}

// ---------------------------------------------------------------------------
// Kernel B2: finalize BN affine
// ---------------------------------------------------------------------------
__global__ void k_final(const float* __restrict__ gamma, const float* __restrict__ beta) {
    const int o = threadIdx.x;
    if (o < 3) {
        const float n = (float)NROWS;
        float mean = g_stats[o] / n;
        float var  = g_stats[3 + o] / n - mean * mean;
        float sc   = gamma[o] * rsqrtf(var + 1e-5f);
        g_coef[o]     = sc;
        g_coef[3 + o] = beta[o] - mean * sc;
    }
}

// ---------------------------------------------------------------------------
// Kernel C: out[512,4096] = (g_y*scale+shift)[512,1536] @ W_fc2^T[1536,4096]
// 128x128x16 tiles, 256 threads, 8x8 microtiles via packed fma.rn.f32x2.
// Double-buffered SMEM, one __syncthreads per k-tile.
// ---------------------------------------------------------------------------
__global__ __launch_bounds__(256) void k_gemm2(const float* __restrict__ W,
                                               float* __restrict__ out) {
    __shared__ float As[2][16][132];
    __shared__ float Bs[2][16][132];

    const int tid = threadIdx.x;
    const int tx = tid & 15;      // N micro index
    const int ty = tid >> 4;      // M micro index
    const int bn = blockIdx.x;    // 0..31
    const int bm = blockIdx.y;    // 0..3

    const int lr = tid >> 2;           // loader row 0..63
    const int lc = (tid & 3) * 4;      // loader col (of 16)

    const float* Ap = g_y + ((size_t)(bm * 128 + lr)) * C3K + lc;
    const float* Bp = W   + ((size_t)(bn * 128 + lr)) * C3K + lc;

    // Packed accumulators: accp[i][j2] = {acc[i][2*j2], acc[i][2*j2+1]}
    unsigned long long accp[8][4];
#pragma unroll
    for (int i = 0; i < 8; i++)
#pragma unroll
        for (int j = 0; j < 4; j++) accp[i][j] = 0ull;

    // Prologue: load & store k-tile 0 into stage 0
    {
        const float sc = g_coef[0], sh = g_coef[3];
        float4 a0  = *(const float4*)(Ap);
        float4 a1  = *(const float4*)(Ap + (size_t)64 * C3K);
        float4 bb0 = *(const float4*)(Bp);
        float4 bb1 = *(const float4*)(Bp + (size_t)64 * C3K);
        As[0][lc + 0][lr]      = a0.x * sc + sh;
        As[0][lc + 1][lr]      = a0.y * sc + sh;
        As[0][lc + 2][lr]      = a0.z * sc + sh;
        As[0][lc + 3][lr]      = a0.w * sc + sh;
        As[0][lc + 0][lr + 64] = a1.x * sc + sh;
        As[0][lc + 1][lr + 64] = a1.y * sc + sh;
        As[0][lc + 2][lr + 64] = a1.z * sc + sh;
        As[0][lc + 3][lr + 64] = a1.w * sc + sh;
        Bs[0][lc + 0][lr]      = bb0.x;
        Bs[0][lc + 1][lr]      = bb0.y;
        Bs[0][lc + 2][lr]      = bb0.z;
        Bs[0][lc + 3][lr]      = bb0.w;
        Bs[0][lc + 0][lr + 64] = bb1.x;
        Bs[0][lc + 1][lr + 64] = bb1.y;
        Bs[0][lc + 2][lr + 64] = bb1.z;
        Bs[0][lc + 3][lr + 64] = bb1.w;
    }
    __syncthreads();

    for (int kt = 0; kt < NKT; kt++) {
        const int s = kt & 1;

        // Prefetch next k-tile from global (overlaps compute below)
        float4 a0, a1, bb0, bb1;
        float sc = 0.f, sh = 0.f;
        const bool more = (kt + 1 < NKT);
        if (more) {
            const int o = (kt + 1) >> 5;
            sc = g_coef[o];
            sh = g_coef[3 + o];
            a0  = *(const float4*)(Ap + (size_t)(kt + 1) * 16);
            a1  = *(const float4*)(Ap + (size_t)(kt + 1) * 16 + (size_t)64 * C3K);
            bb0 = *(const float4*)(Bp + (size_t)(kt + 1) * 16);
            bb1 = *(const float4*)(Bp + (size_t)(kt + 1) * 16 + (size_t)64 * C3K);
        }

        // Compute on stage s
#pragma unroll
        for (int kk = 0; kk < 16; kk++) {
            float4 xa0 = *(const float4*)&As[s][kk][ty * 8];
            float4 xa1 = *(const float4*)&As[s][kk][ty * 8 + 4];
            const unsigned long long* bp =
                (const unsigned long long*)&Bs[s][kk][tx * 8];
            unsigned long long b0 = bp[0], b1 = bp[1], b2 = bp[2], b3 = bp[3];
            float ar[8] = {xa0.x, xa0.y, xa0.z, xa0.w, xa1.x, xa1.y, xa1.z, xa1.w};
#pragma unroll
            for (int i = 0; i < 8; i++) {
                unsigned long long ap;
                asm("mov.b64 %0, {%1, %1};" : "=l"(ap) : "f"(ar[i]));
                asm("fma.rn.f32x2 %0, %1, %2, %0;" : "+l"(accp[i][0]) : "l"(ap), "l"(b0));
                asm("fma.rn.f32x2 %0, %1, %2, %0;" : "+l"(accp[i][1]) : "l"(ap), "l"(b1));
                asm("fma.rn.f32x2 %0, %1, %2, %0;" : "+l"(accp[i][2]) : "l"(ap), "l"(b2));
                asm("fma.rn.f32x2 %0, %1, %2, %0;" : "+l"(accp[i][3]) : "l"(ap), "l"(b3));
            }
        }

        // Store prefetched tile into the other stage
        if (more) {
            const int d = s ^ 1;
            As[d][lc + 0][lr]      = a0.x * sc + sh;
            As[d][lc + 1][lr]      = a0.y * sc + sh;
            As[d][lc + 2][lr]      = a0.z * sc + sh;
            As[d][lc + 3][lr]      = a0.w * sc + sh;
            As[d][lc + 0][lr + 64] = a1.x * sc + sh;
            As[d][lc + 1][lr + 64] = a1.y * sc + sh;
            As[d][lc + 2][lr + 64] = a1.z * sc + sh;
            As[d][lc + 3][lr + 64] = a1.w * sc + sh;
            Bs[d][lc + 0][lr]      = bb0.x;
            Bs[d][lc + 1][lr]      = bb0.y;
            Bs[d][lc + 2][lr]      = bb0.z;
            Bs[d][lc + 3][lr]      = bb0.w;
            Bs[d][lc + 0][lr + 64] = bb1.x;
            Bs[d][lc + 1][lr + 64] = bb1.y;
            Bs[d][lc + 2][lr + 64] = bb1.z;
            Bs[d][lc + 3][lr + 64] = bb1.w;
        }
        __syncthreads();
    }

    float* Cp = out + ((size_t)(bm * 128 + ty * 8)) * DOUT + bn * 128 + tx * 8;
#pragma unroll
    for (int i = 0; i < 8; i++) {
        union { unsigned long long u; float2 f; } c0, c1, c2, c3;
        c0.u = accp[i][0]; c1.u = accp[i][1]; c2.u = accp[i][2]; c3.u = accp[i][3];
        float4 v0 = make_float4(c0.f.x, c0.f.y, c1.f.x, c1.f.y);
        float4 v1 = make_float4(c2.f.x, c2.f.y, c3.f.x, c3.f.y);
        *(float4*)(Cp + (size_t)i * DOUT)     = v0;
        *(float4*)(Cp + (size_t)i * DOUT + 4) = v1;
    }
}

// ---------------------------------------------------------------------------
// Launch
// ---------------------------------------------------------------------------
extern "C" void kernel_launch(void* const* d_in, const int* in_sizes, int n_in,
                              void* d_out, int out_size) {
    const float* x     = (const float*)d_in[0];
    const float* Wemb  = (const float*)d_in[1];
    const float* bemb  = (const float*)d_in[2];
    const float* gamma = (const float*)d_in[3];
    const float* beta  = (const float*)d_in[4];
    const float* Wfc2  = (const float*)d_in[5];
    float* out = (float*)d_out;

    k_embed<<<1184, 256>>>(x, Wemb, bemb);
    k_stats<<<96, 256>>>();
    k_final<<<1, 32>>>(gamma, beta);
    k_gemm2<<<dim3(32, 4), 256>>>(Wfc2, out);
}